// round 6
// baseline (speedup 1.0000x reference)
#include <cuda_runtime.h>
#include <math.h>

#define Bsz 8
#define Tn 256
#define Dm 1024
#define Nn 2048            // B*T
#define MS_W 5120          // 5*D
#define HM 16              // MHA heads
#define DH 64              // MHA head dim
#define HG 8               // GAT heads
#define GD 128             // GAT head dim

// ---------------- scratch (static __device__, no allocation) ----------------
__device__ float g_wt[5u * 7u * 1024u * 1024u];   // transposed conv weights [dil][k][in][out]
__device__ float g_ms[(size_t)Nn * MS_W];         // concat conv features
__device__ float g_zpre[(size_t)Nn * Dm];
__device__ float g_z[(size_t)Nn * Dm];
__device__ float g_q[(size_t)Nn * Dm];
__device__ float g_k[(size_t)Nn * Dm];
__device__ float g_v[(size_t)Nn * Dm];
__device__ float g_scores[(size_t)Bsz * HM * Tn * Tn];
__device__ float g_ctx[(size_t)Nn * Dm];
__device__ float g_att[(size_t)Nn * Dm];
__device__ float g_hg[(size_t)Nn * Dm];
__device__ float g_e1[Nn * HG];
__device__ float g_e2[Nn * HG];
__device__ float g_e2max[HG];

__constant__ int c_dils[5] = {1, 2, 4, 8, 16};

// ---------------- conv weight transpose: w[o][i][k] -> wt[k][i][o] ----------
__global__ void __launch_bounds__(256) transpose_conv_w(const float* __restrict__ w,
                                                        float* __restrict__ wt_d) {
    __shared__ float tile[32][225];
    int o0 = blockIdx.x * 32, i0 = blockIdx.y * 32;
    int tid = threadIdx.x;
#pragma unroll
    for (int r = 0; r < 28; ++r) {
        int e = r * 256 + tid;
        int ol = e / 224, f = e % 224;
        tile[ol][f] = w[(size_t)(o0 + ol) * 7168 + (size_t)i0 * 7 + f];
    }
    __syncthreads();
#pragma unroll
    for (int r = 0; r < 28; ++r) {
        int e = r * 256 + tid;
        int ol = e & 31, il = (e >> 5) & 31, kk = e >> 10;
        wt_d[((size_t)kk << 20) + (size_t)(i0 + il) * 1024 + o0 + ol] = tile[ol][il * 7 + kk];
    }
}

// ---------------- dilated conv bank -> ms  (implicit im2col GEMM) -----------
__global__ void __launch_bounds__(256) conv_ms_kernel(
    const float* __restrict__ x, const float* __restrict__ wt,
    const float* __restrict__ b0, const float* __restrict__ b1,
    const float* __restrict__ b2, const float* __restrict__ b3,
    const float* __restrict__ b4, float* __restrict__ ms) {
    int d = blockIdx.z;
    int dil = c_dils[d];
    int m0 = blockIdx.y * 64, n0 = blockIdx.x * 64;
    __shared__ float As[16][68];
    __shared__ float Bs[16][68];
    int tid = threadIdx.x, tx = tid & 15, ty = tid >> 4;
    float acc[4][4] = {};
    const float* wt_d = wt + (size_t)d * 7u * 1024u * 1024u;
    for (int kk = 0; kk < 7; ++kk) {
        int shift = (kk - 3) * dil;
        const float* wt_k = wt_d + ((size_t)kk << 20);
        for (int it = 0; it < 64; ++it) {
            int i0 = it * 16;
#pragma unroll
            for (int r = 0; r < 4; ++r) {
                int e = r * 256 + tid;
                int ci = e & 15, mm = e >> 4;
                int m = m0 + mm;
                int t = (m & 255) + shift;
                float val = 0.f;
                if ((unsigned)t < 256u)
                    val = x[(size_t)((m & ~255) + t) * 1024 + i0 + ci];
                As[ci][mm] = val;
            }
#pragma unroll
            for (int r = 0; r < 4; ++r) {
                int e = r * 256 + tid;
                int nn = e & 63, ci = e >> 6;
                Bs[ci][nn] = wt_k[(size_t)(i0 + ci) * 1024 + n0 + nn];
            }
            __syncthreads();
#pragma unroll
            for (int c = 0; c < 16; ++c) {
                float a4[4], b4[4];
                *(float4*)a4 = *(const float4*)&As[c][ty * 4];
                *(float4*)b4 = *(const float4*)&Bs[c][tx * 4];
#pragma unroll
                for (int i = 0; i < 4; ++i)
#pragma unroll
                    for (int j = 0; j < 4; ++j) acc[i][j] += a4[i] * b4[j];
            }
            __syncthreads();
        }
    }
    const float* bias = d == 0 ? b0 : d == 1 ? b1 : d == 2 ? b2 : d == 3 ? b3 : b4;
#pragma unroll
    for (int i = 0; i < 4; ++i) {
        int m = m0 + ty * 4 + i;
#pragma unroll
        for (int j = 0; j < 4; ++j) {
            int n = n0 + tx * 4 + j;
            ms[(size_t)m * MS_W + d * 1024 + n] = acc[i][j] + bias[n];
        }
    }
}

// ---------------- generic strided-batched SGEMM:  C = alpha*A*B^T + bias ----
__global__ void __launch_bounds__(256) gemm_nt(
    const float* __restrict__ A, const float* __restrict__ B,
    const float* __restrict__ bias, float* __restrict__ C,
    int M, int N, int Kd,
    long long a_bso, long long a_bsi, int a_rs, int a_cs,
    long long b_bso, long long b_bsi, int b_rs, int b_cs,
    long long c_bso, long long c_bsi, int c_rs,
    int inner, float alpha) {
    int z = blockIdx.z;
    int zo = z / inner, zi = z - zo * inner;
    A += zo * a_bso + zi * a_bsi;
    B += zo * b_bso + zi * b_bsi;
    C += zo * c_bso + zi * c_bsi;
    int m0 = blockIdx.y * 64, n0 = blockIdx.x * 64;
    __shared__ float As[16][68];
    __shared__ float Bs[16][68];
    int tid = threadIdx.x, tx = tid & 15, ty = tid >> 4;
    float acc[4][4] = {};
    for (int k0 = 0; k0 < Kd; k0 += 16) {
#pragma unroll
        for (int r = 0; r < 4; ++r) {
            int e = r * 256 + tid;
            int kk, mm;
            if (a_cs == 1) { kk = e & 15; mm = e >> 4; }
            else           { mm = e & 63; kk = e >> 6; }
            As[kk][mm] = A[(long long)(m0 + mm) * a_rs + (long long)(k0 + kk) * a_cs];
        }
#pragma unroll
        for (int r = 0; r < 4; ++r) {
            int e = r * 256 + tid;
            int kk, nn;
            if (b_cs == 1) { kk = e & 15; nn = e >> 4; }
            else           { nn = e & 63; kk = e >> 6; }
            Bs[kk][nn] = B[(long long)(n0 + nn) * b_rs + (long long)(k0 + kk) * b_cs];
        }
        __syncthreads();
#pragma unroll
        for (int c = 0; c < 16; ++c) {
            float a4[4], b4[4];
            *(float4*)a4 = *(const float4*)&As[c][ty * 4];
            *(float4*)b4 = *(const float4*)&Bs[c][tx * 4];
#pragma unroll
            for (int i = 0; i < 4; ++i)
#pragma unroll
                for (int j = 0; j < 4; ++j) acc[i][j] += a4[i] * b4[j];
        }
        __syncthreads();
    }
#pragma unroll
    for (int i = 0; i < 4; ++i) {
        int m = m0 + ty * 4 + i;
#pragma unroll
        for (int j = 0; j < 4; ++j) {
            int n = n0 + tx * 4 + j;
            float v = acc[i][j] * alpha + (bias ? bias[n] : 0.f);
            C[(long long)m * c_rs + n] = v;
        }
    }
}

// ---------------- LayerNorm + exact GELU (one block per row) ----------------
__global__ void __launch_bounds__(256) ln_gelu_kernel(
    const float* __restrict__ zin, const float* __restrict__ gam,
    const float* __restrict__ bet, float* __restrict__ zout) {
    int r = blockIdx.x, tid = threadIdx.x;
    const float* row = zin + (size_t)r * Dm;
    float v[4];
    float s = 0.f, sq = 0.f;
#pragma unroll
    for (int j = 0; j < 4; ++j) {
        v[j] = row[tid + j * 256];
        s += v[j];
        sq += v[j] * v[j];
    }
    __shared__ float rs[256], rq[256];
    rs[tid] = s; rq[tid] = sq;
    __syncthreads();
    for (int st = 128; st > 0; st >>= 1) {
        if (tid < st) { rs[tid] += rs[tid + st]; rq[tid] += rq[tid + st]; }
        __syncthreads();
    }
    float mean = rs[0] * (1.f / 1024.f);
    float var = rq[0] * (1.f / 1024.f) - mean * mean;
    float inv = rsqrtf(var + 1e-5f);
#pragma unroll
    for (int j = 0; j < 4; ++j) {
        int c = tid + j * 256;
        float y = (v[j] - mean) * inv * gam[c] + bet[c];
        zout[(size_t)r * Dm + c] = 0.5f * y * (1.f + erff(y * 0.70710678118654752f));
    }
}

// ---------------- row softmax, length 256 -----------------------------------
__global__ void __launch_bounds__(256) softmax256(float* __restrict__ sc) {
    int r = blockIdx.x, tid = threadIdx.x;
    float* row = sc + (size_t)r * 256;
    float v = row[tid];
    __shared__ float red[256];
    red[tid] = v;
    __syncthreads();
    for (int st = 128; st > 0; st >>= 1) {
        if (tid < st) red[tid] = fmaxf(red[tid], red[tid + st]);
        __syncthreads();
    }
    float m = red[0];
    __syncthreads();
    float e = expf(v - m);
    red[tid] = e;
    __syncthreads();
    for (int st = 128; st > 0; st >>= 1) {
        if (tid < st) red[tid] += red[tid + st];
        __syncthreads();
    }
    row[tid] = e / red[0];
}

// ---------------- GAT: e1,e2 dots (warp per head) ---------------------------
__global__ void __launch_bounds__(256) e1e2_kernel(
    const float* __restrict__ hg, const float* __restrict__ a1,
    const float* __restrict__ a2, float* __restrict__ e1, float* __restrict__ e2) {
    int n = blockIdx.x, tid = threadIdx.x;
    int h = tid >> 5, lane = tid & 31;
    const float* base = hg + (size_t)n * Dm + h * GD;
    float s1 = 0.f, s2 = 0.f;
#pragma unroll
    for (int j = 0; j < 4; ++j) {
        int d = lane + j * 32;
        float v = base[d];
        s1 += v * a1[d];
        s2 += v * a2[d];
    }
#pragma unroll
    for (int off = 16; off > 0; off >>= 1) {
        s1 += __shfl_down_sync(0xffffffffu, s1, off);
        s2 += __shfl_down_sync(0xffffffffu, s2, off);
    }
    if (lane == 0) { e1[n * HG + h] = s1; e2[n * HG + h] = s2; }
}

__global__ void __launch_bounds__(256) e2max_kernel(const float* __restrict__ e2,
                                                    float* __restrict__ e2m) {
    __shared__ float red[256];
    int h = blockIdx.x, tid = threadIdx.x;
    float m = -3.4e38f;
    for (int n = tid; n < Nn; n += 256) m = fmaxf(m, e2[n * HG + h]);
    red[tid] = m;
    __syncthreads();
    for (int st = 128; st > 0; st >>= 1) {
        if (tid < st) red[tid] = fmaxf(red[tid], red[tid + st]);
        __syncthreads();
    }
    if (tid == 0) e2m[h] = red[0];
}

// ---------------- GAT aggregate + ELU + residual ----------------------------
#define TI 16
__global__ void __launch_bounds__(256) gat_agg_kernel(
    const float* __restrict__ hg, const float* __restrict__ e1,
    const float* __restrict__ e2, const float* __restrict__ e2m,
    const float* __restrict__ feat, float* __restrict__ out) {
    int h = blockIdx.y;
    int i0 = blockIdx.x * TI;
    int tid = threadIdx.x;
    __shared__ float ws[TI][129];
    __shared__ float e2s[128];
    __shared__ float sm_i[TI], ss_i[TI];
    __shared__ float red[TI][17];

    if (tid < TI) {
        float s = e1[(i0 + tid) * HG + h];
        ss_i[tid] = s;
        float vmx = s + e2m[h];
        sm_i[tid] = vmx > 0.f ? vmx : 0.2f * vmx;
    }
    __syncthreads();

    int d = tid & 127;
    int g = tid >> 7;           // 0/1
    int i_base = g * 8;
    int i_w = tid & 15;
    int jgrp = tid >> 4;        // 0..15
    float s_i = ss_i[i_w];
    float m_i = sm_i[i_w];

    float acc[8] = {0.f, 0.f, 0.f, 0.f, 0.f, 0.f, 0.f, 0.f};
    float psum = 0.f;

    for (int jc = 0; jc < Nn / 128; ++jc) {
        if (tid < 128) e2s[tid] = e2[(jc * 128 + tid) * HG + h];
        __syncthreads();
#pragma unroll
        for (int s = 0; s < 8; ++s) {
            int jl = jgrp * 8 + s;
            float vv = s_i + e2s[jl];
            float lr = vv > 0.f ? vv : 0.2f * vv;
            float w = expf(lr - m_i);
            ws[i_w][jl] = w;
            psum += w;
        }
        __syncthreads();
        const float* hgp = hg + (size_t)(jc * 128) * Dm + h * GD + d;
#pragma unroll 4
        for (int jl = 0; jl < 128; ++jl) {
            float hv = hgp[(size_t)jl * Dm];
#pragma unroll
            for (int ii = 0; ii < 8; ++ii) acc[ii] += ws[i_base + ii][jl] * hv;
        }
        __syncthreads();
    }
    red[i_w][jgrp] = psum;
    __syncthreads();
    if (tid < TI) {
        float s = 0.f;
        for (int jg = 0; jg < 16; ++jg) s += red[tid][jg];
        red[tid][16] = s;
    }
    __syncthreads();
#pragma unroll
    for (int ii = 0; ii < 8; ++ii) {
        int i = i0 + i_base + ii;
        float v = acc[ii] / red[i_base + ii][16];
        float o = v > 0.f ? v : expm1f(v);
        size_t idx = (size_t)i * Dm + h * GD + d;
        out[idx] = o + feat[idx];
    }
}

// ---------------- host orchestration ----------------------------------------
extern "C" void kernel_launch(void* const* d_in, const int* in_sizes, int n_in,
                              void* d_out, int out_size) {
    const float* features = (const float*)d_in[0];
    const float* conv_w[5];
    const float* conv_b[5];
    // Adaptive input-order detection: setup_inputs() interleaves conv_w/conv_b
    // (w0,b0,w1,b1,...). Detect via element counts: a conv weight has 1024*1024*7
    // elements, a bias 1024.
    bool interleaved = (in_sizes[2] == 1024);
    for (int i = 0; i < 5; ++i) {
        if (interleaved) {
            conv_w[i] = (const float*)d_in[1 + 2 * i];
            conv_b[i] = (const float*)d_in[2 + 2 * i];
        } else {
            conv_w[i] = (const float*)d_in[1 + i];
            conv_b[i] = (const float*)d_in[6 + i];
        }
    }
    const float* fp_w = (const float*)d_in[11];
    const float* fp_b = (const float*)d_in[12];
    const float* ln_g = (const float*)d_in[13];
    const float* ln_b = (const float*)d_in[14];
    const float* wq = (const float*)d_in[15];
    const float* bq = (const float*)d_in[16];
    const float* wk = (const float*)d_in[17];
    const float* bk = (const float*)d_in[18];
    const float* wv = (const float*)d_in[19];
    const float* bv = (const float*)d_in[20];
    const float* wo = (const float*)d_in[21];
    const float* bo = (const float*)d_in[22];
    const float* gat_w = (const float*)d_in[23];
    const float* gat_b = (const float*)d_in[24];
    const float* ga1 = (const float*)d_in[25];
    const float* ga2 = (const float*)d_in[26];
    float* out = (float*)d_out;

    float *wt, *ms, *zpre, *z, *q, *k, *v, *sc, *ctx, *att, *hg, *e1, *e2, *e2m;
    cudaGetSymbolAddress((void**)&wt, g_wt);
    cudaGetSymbolAddress((void**)&ms, g_ms);
    cudaGetSymbolAddress((void**)&zpre, g_zpre);
    cudaGetSymbolAddress((void**)&z, g_z);
    cudaGetSymbolAddress((void**)&q, g_q);
    cudaGetSymbolAddress((void**)&k, g_k);
    cudaGetSymbolAddress((void**)&v, g_v);
    cudaGetSymbolAddress((void**)&sc, g_scores);
    cudaGetSymbolAddress((void**)&ctx, g_ctx);
    cudaGetSymbolAddress((void**)&att, g_att);
    cudaGetSymbolAddress((void**)&hg, g_hg);
    cudaGetSymbolAddress((void**)&e1, g_e1);
    cudaGetSymbolAddress((void**)&e2, g_e2);
    cudaGetSymbolAddress((void**)&e2m, g_e2max);

    // 1) conv weight transpose
    for (int dd = 0; dd < 5; ++dd)
        transpose_conv_w<<<dim3(32, 32), 256>>>(conv_w[dd], wt + (size_t)dd * 7u * 1024u * 1024u);

    // 2) dilated conv bank -> ms (B,T,5D)
    conv_ms_kernel<<<dim3(16, 32, 5), 256>>>(features, wt, conv_b[0], conv_b[1],
                                             conv_b[2], conv_b[3], conv_b[4], ms);

    // 3) fusion projection: zpre = ms @ fp_w^T + fp_b
    gemm_nt<<<dim3(16, 32, 1), 256>>>(ms, fp_w, fp_b, zpre, Nn, Dm, MS_W,
                                      0, 0, MS_W, 1, 0, 0, MS_W, 1, 0, 0, Dm, 1, 1.f);

    // 4) LayerNorm + GELU
    ln_gelu_kernel<<<Nn, 256>>>(zpre, ln_g, ln_b, z);

    // 5) Q,K,V projections
    gemm_nt<<<dim3(16, 32, 1), 256>>>(z, wq, bq, q, Nn, Dm, Dm,
                                      0, 0, Dm, 1, 0, 0, Dm, 1, 0, 0, Dm, 1, 1.f);
    gemm_nt<<<dim3(16, 32, 1), 256>>>(z, wk, bk, k, Nn, Dm, Dm,
                                      0, 0, Dm, 1, 0, 0, Dm, 1, 0, 0, Dm, 1, 1.f);
    gemm_nt<<<dim3(16, 32, 1), 256>>>(z, wv, bv, v, Nn, Dm, Dm,
                                      0, 0, Dm, 1, 0, 0, Dm, 1, 0, 0, Dm, 1, 1.f);

    // 6) scores[b,h] = 0.125 * q_bh @ k_bh^T  (batch = 128, inner = 16 heads)
    gemm_nt<<<dim3(4, 4, 128), 256>>>(q, k, nullptr, sc, Tn, Tn, DH,
                                      (long long)Tn * Dm, DH, Dm, 1,
                                      (long long)Tn * Dm, DH, Dm, 1,
                                      (long long)HM * Tn * Tn, (long long)Tn * Tn, Tn,
                                      HM, 0.125f);

    // 7) softmax over keys
    softmax256<<<Bsz * HM * Tn, 256>>>(sc);

    // 8) ctx[b,q,h,:] = attn @ v
    gemm_nt<<<dim3(1, 4, 128), 256>>>(sc, v, nullptr, ctx, Tn, DH, Tn,
                                      (long long)HM * Tn * Tn, (long long)Tn * Tn, Tn, 1,
                                      (long long)Tn * Dm, DH, 1, Dm,
                                      (long long)Tn * Dm, DH, Dm,
                                      HM, 1.f);

    // 9) output projection
    gemm_nt<<<dim3(16, 32, 1), 256>>>(ctx, wo, bo, att, Nn, Dm, Dm,
                                      0, 0, Dm, 1, 0, 0, Dm, 1, 0, 0, Dm, 1, 1.f);

    // 10) GAT projection
    gemm_nt<<<dim3(16, 32, 1), 256>>>(att, gat_w, gat_b, hg, Nn, Dm, Dm,
                                      0, 0, Dm, 1, 0, 0, Dm, 1, 0, 0, Dm, 1, 1.f);

    // 11) attention logits pieces
    e1e2_kernel<<<Nn, 256>>>(hg, ga1, ga2, e1, e2);
    e2max_kernel<<<HG, 256>>>(e2, e2m);

    // 12) GAT aggregate + ELU + residual -> out
    gat_agg_kernel<<<dim3(Nn / TI, HG), 256>>>(hg, e1, e2, e2m, features, out);
}

// round 9
// speedup vs baseline: 2.2809x; 2.2809x over previous
#include <cuda_runtime.h>
#include <cuda_bf16.h>
#include <math.h>
#include <stdint.h>

#define Bsz 8
#define Tn 256
#define Dm 1024
#define Nn 2048
#define MS_W 5120
#define HM 16
#define DH 64
#define HG 8
#define GD 128

// ===================== portable PTX helpers (compute_103-safe) ==============
__device__ __forceinline__ uint32_t smem_u32(const void* p) {
    uint32_t a;
    asm("{ .reg .u64 t; cvta.to.shared.u64 t, %1; cvt.u32.u64 %0, t; }" : "=r"(a) : "l"(p));
    return a;
}
#define SMEM_SWZ128(x) ((x) ^ (((x) >> 3) & 0x70))

__device__ __forceinline__ void cp16(uint32_t dst, const void* src, int sz) {
    asm volatile("cp.async.cg.shared.global [%0], [%1], 16, %2;" ::"r"(dst), "l"(src), "r"(sz));
}
#define CP_COMMIT() asm volatile("cp.async.commit_group;" ::: "memory")
#define CP_WAIT1() asm volatile("cp.async.wait_group 1;" ::: "memory")
#define CP_WAIT0() asm volatile("cp.async.wait_group 0;" ::: "memory")

__device__ __forceinline__ void ldsm4(uint32_t& r0, uint32_t& r1, uint32_t& r2, uint32_t& r3,
                                      uint32_t a) {
    asm volatile("ldmatrix.sync.aligned.m8n8.x4.shared.b16 {%0,%1,%2,%3}, [%4];"
                 : "=r"(r0), "=r"(r1), "=r"(r2), "=r"(r3) : "r"(a));
}
__device__ __forceinline__ void mma16816(float* d, const uint32_t* a, const uint32_t* b) {
    asm volatile(
        "mma.sync.aligned.m16n8k16.row.col.f32.bf16.bf16.f32 "
        "{%0,%1,%2,%3}, {%4,%5,%6,%7}, {%8,%9}, {%0,%1,%2,%3};"
        : "+f"(d[0]), "+f"(d[1]), "+f"(d[2]), "+f"(d[3])
        : "r"(a[0]), "r"(a[1]), "r"(a[2]), "r"(a[3]), "r"(b[0]), "r"(b[1]));
}

// ===================== scratch =============================================
__device__ __align__(16) __nv_bfloat16 g_x3[(size_t)Nn * 3072];
__device__ __align__(16) __nv_bfloat16 g_ms3[(size_t)Nn * 15360];
__device__ __align__(16) __nv_bfloat16 g_z3[(size_t)Nn * 3072];
__device__ __align__(16) __nv_bfloat16 g_ctx3[(size_t)Nn * 3072];
__device__ __align__(16) __nv_bfloat16 g_att3[(size_t)Nn * 3072];
__device__ __align__(16) __nv_bfloat16 g_wc3[(size_t)5 * 1024 * 21504];
__device__ __align__(16) __nv_bfloat16 g_fpw3[(size_t)1024 * 15360];
__device__ __align__(16) __nv_bfloat16 g_wq3[(size_t)1024 * 3072];
__device__ __align__(16) __nv_bfloat16 g_wk3[(size_t)1024 * 3072];
__device__ __align__(16) __nv_bfloat16 g_wv3[(size_t)1024 * 3072];
__device__ __align__(16) __nv_bfloat16 g_wo3[(size_t)1024 * 3072];
__device__ __align__(16) __nv_bfloat16 g_gw3[(size_t)1024 * 3072];

__device__ float g_zpre[(size_t)Nn * Dm];
__device__ float g_q[(size_t)Nn * Dm];
__device__ float g_k[(size_t)Nn * Dm];
__device__ float g_v[(size_t)Nn * Dm];
__device__ float g_scores[(size_t)Bsz * HM * Tn * Tn];
__device__ float g_ctx[(size_t)Nn * Dm];
__device__ float g_hg[(size_t)Nn * Dm];
__device__ float g_e1[Nn * HG];
__device__ float g_e2[Nn * HG];
__device__ float g_e2max[HG];

__constant__ int c_dils[5] = {1, 2, 4, 8, 16};

// ===================== split conversions ====================================
__global__ void __launch_bounds__(256) split_mat(const float* __restrict__ in,
                                                 __nv_bfloat16* __restrict__ out,
                                                 int Cd, int patB) {
    int r = blockIdx.x;
    size_t ib = (size_t)r * Cd, ob = (size_t)r * 3 * Cd;
    for (int c = threadIdx.x; c < Cd; c += 256) {
        float x = in[ib + c];
        __nv_bfloat16 h = __float2bfloat16(x);
        __nv_bfloat16 l = __float2bfloat16(x - __bfloat162float(h));
        if (patB) { out[ob + c] = h; out[ob + Cd + c] = h; out[ob + 2 * Cd + c] = l; }
        else      { out[ob + c] = h; out[ob + Cd + c] = l; out[ob + 2 * Cd + c] = h; }
    }
}

// conv weight w[o][i][k] -> wc3[o][kk*3072 + {i:hi, 1024+i:hi, 2048+i:lo}]
__global__ void __launch_bounds__(256) split_conv_w(const float* __restrict__ w,
                                                    __nv_bfloat16* __restrict__ out) {
    int o = blockIdx.x;
    for (int i = threadIdx.x; i < 1024; i += 256) {
#pragma unroll
        for (int kk = 0; kk < 7; ++kk) {
            float x = w[(size_t)o * 7168 + i * 7 + kk];
            __nv_bfloat16 h = __float2bfloat16(x);
            __nv_bfloat16 l = __float2bfloat16(x - __bfloat162float(h));
            size_t base = (size_t)o * 21504 + kk * 3072;
            out[base + i] = h; out[base + 1024 + i] = h; out[base + 2048 + i] = l;
        }
    }
}

// ===================== warp-MMA compute core ================================
// smem stage: A tile 128x64 bf16 (swizzled 128B rows) at +0, B tile at +16384.
__device__ __forceinline__ void mma_stage(uint32_t sA, uint32_t sB, int warp_m, int warp_n,
                                          int lane, float acc[4][4][4]) {
    int lrow = lane & 15;
    int lcol = (lane >> 4) * 16;   // byte offset within 32-byte kstep chunk
#pragma unroll
    for (int ks = 0; ks < 4; ++ks) {
        uint32_t a[4][4];
        uint32_t b[4][2];
#pragma unroll
        for (int mi = 0; mi < 4; ++mi) {
            int row = warp_m * 64 + mi * 16 + lrow;
            uint32_t addr = sA + SMEM_SWZ128(row * 128 + ks * 32 + lcol);
            ldsm4(a[mi][0], a[mi][1], a[mi][2], a[mi][3], addr);
        }
#pragma unroll
        for (int nj = 0; nj < 2; ++nj) {
            int row = warp_n * 32 + nj * 16 + lrow;
            uint32_t addr = sB + SMEM_SWZ128(row * 128 + ks * 32 + lcol);
            uint32_t r0, r1, r2, r3;
            ldsm4(r0, r1, r2, r3, addr);
            b[nj * 2][0] = r0;     b[nj * 2][1] = r2;
            b[nj * 2 + 1][0] = r1; b[nj * 2 + 1][1] = r3;
        }
#pragma unroll
        for (int mi = 0; mi < 4; ++mi)
#pragma unroll
            for (int ni = 0; ni < 4; ++ni)
                mma16816(acc[mi][ni], a[mi], b[ni]);
    }
}

// ===================== conv GEMM (implicit shift, K'=21504) =================
__global__ void __launch_bounds__(256) conv_tc(
    const __nv_bfloat16* __restrict__ x3, const __nv_bfloat16* __restrict__ wc3,
    const float* __restrict__ b0, const float* __restrict__ b1,
    const float* __restrict__ b2, const float* __restrict__ b3,
    const float* __restrict__ b4, __nv_bfloat16* __restrict__ ms3) {
    extern __shared__ __align__(16) char smem[];
    uint32_t sb = smem_u32(smem);
    int tid = threadIdx.x, wid = tid >> 5, lane = tid & 31;
    int warp_m = wid >> 2, warp_n = wid & 3;
    int n0 = blockIdx.x * 128, m0 = blockIdx.y * 128;
    int dz = blockIdx.z, dil = c_dils[dz];
    const __nv_bfloat16* B3 = wc3 + (size_t)dz * 1024 * 21504;
    int seqbase = m0 & ~255, trow0 = m0 & 255;

    int ar = tid >> 3, ac = tid & 7;   // loader: rows step 32 per 256 threads

    float acc[4][4][4] = {};

    const int nch = 21504 / 64;   // 336
    // ---- loader lambda-ish macro ----
#define CONV_LOAD(it, stg) do {                                                            \
        int k0 = (it) << 6;                                                                \
        int kk = k0 / 3072;                                                                \
        int inner0 = k0 - kk * 3072;                                                       \
        int shift = (kk - 3) * dil;                                                        \
        uint32_t abase = sb + (stg) * 32768u;                                              \
        uint32_t bbase = abase + 16384u;                                                   \
        _Pragma("unroll")                                                                  \
        for (int rr = 0; rr < 4; ++rr) {                                                   \
            int r = ar + rr * 32;                                                          \
            int t = trow0 + r + shift;                                                     \
            int ok = ((unsigned)t < 256u) ? 16 : 0;                                        \
            int tc2 = ok ? t : 0;                                                          \
            cp16(abase + SMEM_SWZ128(r * 128 + ac * 16),                                   \
                 x3 + (size_t)(seqbase + tc2) * 3072 + inner0 + ac * 8, ok);               \
            cp16(bbase + SMEM_SWZ128(r * 128 + ac * 16),                                   \
                 B3 + (size_t)(n0 + r) * 21504 + k0 + ac * 8, 16);                         \
        }                                                                                  \
        CP_COMMIT();                                                                       \
    } while (0)

    CONV_LOAD(0, 0);
    for (int it = 0; it < nch; ++it) {
        int stg = it & 1;
        if (it + 1 < nch) { CONV_LOAD(it + 1, 1 - stg); CP_WAIT1(); }
        else CP_WAIT0();
        __syncthreads();
        mma_stage(sb + stg * 32768u, sb + stg * 32768u + 16384u, warp_m, warp_n, lane, acc);
        __syncthreads();
    }
#undef CONV_LOAD

    const float* bias = dz == 0 ? b0 : dz == 1 ? b1 : dz == 2 ? b2 : dz == 3 ? b3 : b4;
    int lr = lane >> 2, lc = (lane & 3) * 2;
#pragma unroll
    for (int mi = 0; mi < 4; ++mi)
#pragma unroll
        for (int ni = 0; ni < 4; ++ni)
#pragma unroll
            for (int e = 0; e < 4; ++e) {
                int m = m0 + warp_m * 64 + mi * 16 + lr + ((e >> 1) ? 8 : 0);
                int n = n0 + warp_n * 32 + ni * 8 + lc + (e & 1);
                float v = acc[mi][ni][e] + bias[n];
                __nv_bfloat16 h = __float2bfloat16(v);
                __nv_bfloat16 l = __float2bfloat16(v - __bfloat162float(h));
                size_t rbase = (size_t)m * 15360;
                size_t col = (size_t)dz * 1024 + n;
                ms3[rbase + col] = h;
                ms3[rbase + 5120 + col] = l;
                ms3[rbase + 10240 + col] = h;
            }
}

// ===================== dense GEMM: C = A3 . B3^T + bias =====================
__global__ void __launch_bounds__(256) dense_tc(
    const __nv_bfloat16* __restrict__ A3, const __nv_bfloat16* __restrict__ B3,
    const float* __restrict__ bias, float* __restrict__ Cf,
    __nv_bfloat16* __restrict__ C3, int Kp) {
    extern __shared__ __align__(16) char smem[];
    uint32_t sb = smem_u32(smem);
    int tid = threadIdx.x, wid = tid >> 5, lane = tid & 31;
    int warp_m = wid >> 2, warp_n = wid & 3;
    int n0 = blockIdx.x * 128, m0 = blockIdx.y * 128;
    int ar = tid >> 3, ac = tid & 7;

    float acc[4][4][4] = {};
    int nch = Kp >> 6;

#define DENSE_LOAD(it, stg) do {                                                           \
        int k0 = (it) << 6;                                                                \
        uint32_t abase = sb + (stg) * 32768u;                                              \
        uint32_t bbase = abase + 16384u;                                                   \
        _Pragma("unroll")                                                                  \
        for (int rr = 0; rr < 4; ++rr) {                                                   \
            int r = ar + rr * 32;                                                          \
            cp16(abase + SMEM_SWZ128(r * 128 + ac * 16),                                   \
                 A3 + (size_t)(m0 + r) * Kp + k0 + ac * 8, 16);                            \
            cp16(bbase + SMEM_SWZ128(r * 128 + ac * 16),                                   \
                 B3 + (size_t)(n0 + r) * Kp + k0 + ac * 8, 16);                            \
        }                                                                                  \
        CP_COMMIT();                                                                       \
    } while (0)

    DENSE_LOAD(0, 0);
    for (int it = 0; it < nch; ++it) {
        int stg = it & 1;
        if (it + 1 < nch) { DENSE_LOAD(it + 1, 1 - stg); CP_WAIT1(); }
        else CP_WAIT0();
        __syncthreads();
        mma_stage(sb + stg * 32768u, sb + stg * 32768u + 16384u, warp_m, warp_n, lane, acc);
        __syncthreads();
    }
#undef DENSE_LOAD

    int lr = lane >> 2, lc = (lane & 3) * 2;
#pragma unroll
    for (int mi = 0; mi < 4; ++mi)
#pragma unroll
        for (int ni = 0; ni < 4; ++ni)
#pragma unroll
            for (int e = 0; e < 4; ++e) {
                int m = m0 + warp_m * 64 + mi * 16 + lr + ((e >> 1) ? 8 : 0);
                int n = n0 + warp_n * 32 + ni * 8 + lc + (e & 1);
                float v = acc[mi][ni][e] + bias[n];
                if (C3) {
                    __nv_bfloat16 h = __float2bfloat16(v);
                    __nv_bfloat16 l = __float2bfloat16(v - __bfloat162float(h));
                    size_t base = (size_t)m * 3072;
                    C3[base + n] = h; C3[base + 1024 + n] = l; C3[base + 2048 + n] = h;
                } else {
                    Cf[(size_t)m * 1024 + n] = v;
                }
            }
}

// ===================== SIMT attention GEMM (small) ==========================
__global__ void __launch_bounds__(256) gemm_nt(
    const float* __restrict__ A, const float* __restrict__ B,
    const float* __restrict__ bias, float* __restrict__ C,
    int M, int N, int Kd,
    long long a_bso, long long a_bsi, int a_rs, int a_cs,
    long long b_bso, long long b_bsi, int b_rs, int b_cs,
    long long c_bso, long long c_bsi, int c_rs,
    int inner, float alpha) {
    int z = blockIdx.z;
    int zo = z / inner, zi = z - zo * inner;
    A += zo * a_bso + zi * a_bsi;
    B += zo * b_bso + zi * b_bsi;
    C += zo * c_bso + zi * c_bsi;
    int m0 = blockIdx.y * 64, n0 = blockIdx.x * 64;
    __shared__ float As[16][68];
    __shared__ float Bs[16][68];
    int tid = threadIdx.x, tx = tid & 15, ty = tid >> 4;
    float acc[4][4] = {};
    for (int k0 = 0; k0 < Kd; k0 += 16) {
#pragma unroll
        for (int r = 0; r < 4; ++r) {
            int e = r * 256 + tid;
            int kk, mm;
            if (a_cs == 1) { kk = e & 15; mm = e >> 4; }
            else           { mm = e & 63; kk = e >> 6; }
            As[kk][mm] = A[(long long)(m0 + mm) * a_rs + (long long)(k0 + kk) * a_cs];
        }
#pragma unroll
        for (int r = 0; r < 4; ++r) {
            int e = r * 256 + tid;
            int kk, nn;
            if (b_cs == 1) { kk = e & 15; nn = e >> 4; }
            else           { nn = e & 63; kk = e >> 6; }
            Bs[kk][nn] = B[(long long)(n0 + nn) * b_rs + (long long)(k0 + kk) * b_cs];
        }
        __syncthreads();
#pragma unroll
        for (int c = 0; c < 16; ++c) {
            float a4[4], b4[4];
            *(float4*)a4 = *(const float4*)&As[c][ty * 4];
            *(float4*)b4 = *(const float4*)&Bs[c][tx * 4];
#pragma unroll
            for (int i = 0; i < 4; ++i)
#pragma unroll
                for (int j = 0; j < 4; ++j) acc[i][j] += a4[i] * b4[j];
        }
        __syncthreads();
    }
#pragma unroll
    for (int i = 0; i < 4; ++i) {
        int m = m0 + ty * 4 + i;
#pragma unroll
        for (int j = 0; j < 4; ++j) {
            int n = n0 + tx * 4 + j;
            float v = acc[i][j] * alpha + (bias ? bias[n] : 0.f);
            C[(long long)m * c_rs + n] = v;
        }
    }
}

// ===================== LN + GELU -> z3 triple ===============================
__global__ void __launch_bounds__(256) ln_gelu_kernel(
    const float* __restrict__ zin, const float* __restrict__ gam,
    const float* __restrict__ bet, __nv_bfloat16* __restrict__ z3) {
    int r = blockIdx.x, tid = threadIdx.x;
    const float* row = zin + (size_t)r * Dm;
    float v[4];
    float s = 0.f, sq = 0.f;
#pragma unroll
    for (int j = 0; j < 4; ++j) {
        v[j] = row[tid + j * 256];
        s += v[j];
        sq += v[j] * v[j];
    }
    __shared__ float rs[256], rq[256];
    rs[tid] = s; rq[tid] = sq;
    __syncthreads();
    for (int st = 128; st > 0; st >>= 1) {
        if (tid < st) { rs[tid] += rs[tid + st]; rq[tid] += rq[tid + st]; }
        __syncthreads();
    }
    float mean = rs[0] * (1.f / 1024.f);
    float var = rq[0] * (1.f / 1024.f) - mean * mean;
    float inv = rsqrtf(var + 1e-5f);
    size_t ob = (size_t)r * 3072;
#pragma unroll
    for (int j = 0; j < 4; ++j) {
        int c = tid + j * 256;
        float y = (v[j] - mean) * inv * gam[c] + bet[c];
        float ge = 0.5f * y * (1.f + erff(y * 0.70710678118654752f));
        __nv_bfloat16 h = __float2bfloat16(ge);
        __nv_bfloat16 l = __float2bfloat16(ge - __bfloat162float(h));
        z3[ob + c] = h; z3[ob + 1024 + c] = l; z3[ob + 2048 + c] = h;
    }
}

// ===================== softmax / GAT pieces =================================
__global__ void __launch_bounds__(256) softmax256(float* __restrict__ sc) {
    int r = blockIdx.x, tid = threadIdx.x;
    float* row = sc + (size_t)r * 256;
    float v = row[tid];
    __shared__ float red[256];
    red[tid] = v;
    __syncthreads();
    for (int st = 128; st > 0; st >>= 1) {
        if (tid < st) red[tid] = fmaxf(red[tid], red[tid + st]);
        __syncthreads();
    }
    float m = red[0];
    __syncthreads();
    float e = expf(v - m);
    red[tid] = e;
    __syncthreads();
    for (int st = 128; st > 0; st >>= 1) {
        if (tid < st) red[tid] += red[tid + st];
        __syncthreads();
    }
    row[tid] = e / red[0];
}

__global__ void __launch_bounds__(256) e1e2_kernel(
    const float* __restrict__ hg, const float* __restrict__ a1,
    const float* __restrict__ a2, float* __restrict__ e1, float* __restrict__ e2) {
    int n = blockIdx.x, tid = threadIdx.x;
    int h = tid >> 5, lane = tid & 31;
    const float* base = hg + (size_t)n * Dm + h * GD;
    float s1 = 0.f, s2 = 0.f;
#pragma unroll
    for (int j = 0; j < 4; ++j) {
        int d = lane + j * 32;
        float v = base[d];
        s1 += v * a1[d];
        s2 += v * a2[d];
    }
#pragma unroll
    for (int off = 16; off > 0; off >>= 1) {
        s1 += __shfl_down_sync(0xffffffffu, s1, off);
        s2 += __shfl_down_sync(0xffffffffu, s2, off);
    }
    if (lane == 0) { e1[n * HG + h] = s1; e2[n * HG + h] = s2; }
}

__global__ void __launch_bounds__(256) e2max_kernel(const float* __restrict__ e2,
                                                    float* __restrict__ e2m) {
    __shared__ float red[256];
    int h = blockIdx.x, tid = threadIdx.x;
    float m = -3.4e38f;
    for (int n = tid; n < Nn; n += 256) m = fmaxf(m, e2[n * HG + h]);
    red[tid] = m;
    __syncthreads();
    for (int st = 128; st > 0; st >>= 1) {
        if (tid < st) red[tid] = fmaxf(red[tid], red[tid + st]);
        __syncthreads();
    }
    if (tid == 0) e2m[h] = red[0];
}

#define TI 16
__global__ void __launch_bounds__(256) gat_agg_kernel(
    const float* __restrict__ hg, const float* __restrict__ e1,
    const float* __restrict__ e2, const float* __restrict__ e2m,
    const float* __restrict__ feat, float* __restrict__ out) {
    int h = blockIdx.y;
    int i0 = blockIdx.x * TI;
    int tid = threadIdx.x;
    __shared__ float ws[TI][129];
    __shared__ float e2s[128];
    __shared__ float sm_i[TI], ss_i[TI];
    __shared__ float red[TI][17];

    if (tid < TI) {
        float s = e1[(i0 + tid) * HG + h];
        ss_i[tid] = s;
        float vmx = s + e2m[h];
        sm_i[tid] = vmx > 0.f ? vmx : 0.2f * vmx;
    }
    __syncthreads();

    int d = tid & 127;
    int g = tid >> 7;
    int i_base = g * 8;
    int i_w = tid & 15;
    int jgrp = tid >> 4;
    float s_i = ss_i[i_w];
    float m_i = sm_i[i_w];

    float acc[8] = {0.f, 0.f, 0.f, 0.f, 0.f, 0.f, 0.f, 0.f};
    float psum = 0.f;

    for (int jc = 0; jc < Nn / 128; ++jc) {
        if (tid < 128) e2s[tid] = e2[(jc * 128 + tid) * HG + h];
        __syncthreads();
#pragma unroll
        for (int s = 0; s < 8; ++s) {
            int jl = jgrp * 8 + s;
            float vv = s_i + e2s[jl];
            float lr = vv > 0.f ? vv : 0.2f * vv;
            float w = expf(lr - m_i);
            ws[i_w][jl] = w;
            psum += w;
        }
        __syncthreads();
        const float* hgp = hg + (size_t)(jc * 128) * Dm + h * GD + d;
#pragma unroll 4
        for (int jl = 0; jl < 128; ++jl) {
            float hv = hgp[(size_t)jl * Dm];
#pragma unroll
            for (int ii = 0; ii < 8; ++ii) acc[ii] += ws[i_base + ii][jl] * hv;
        }
        __syncthreads();
    }
    red[i_w][jgrp] = psum;
    __syncthreads();
    if (tid < TI) {
        float s = 0.f;
        for (int jg = 0; jg < 16; ++jg) s += red[tid][jg];
        red[tid][16] = s;
    }
    __syncthreads();
#pragma unroll
    for (int ii = 0; ii < 8; ++ii) {
        int i = i0 + i_base + ii;
        float v = acc[ii] / red[i_base + ii][16];
        float o = v > 0.f ? v : expm1f(v);
        size_t idx = (size_t)i * Dm + h * GD + d;
        out[idx] = o + feat[idx];
    }
}

// ===================== host orchestration ===================================
#define TC_SMEM 65536

extern "C" void kernel_launch(void* const* d_in, const int* in_sizes, int n_in,
                              void* d_out, int out_size) {
    const float* features = (const float*)d_in[0];
    const float* conv_w[5];
    const float* conv_b[5];
    bool interleaved = (in_sizes[2] == 1024);
    for (int i = 0; i < 5; ++i) {
        if (interleaved) {
            conv_w[i] = (const float*)d_in[1 + 2 * i];
            conv_b[i] = (const float*)d_in[2 + 2 * i];
        } else {
            conv_w[i] = (const float*)d_in[1 + i];
            conv_b[i] = (const float*)d_in[6 + i];
        }
    }
    const float* fp_w = (const float*)d_in[11];
    const float* fp_b = (const float*)d_in[12];
    const float* ln_g = (const float*)d_in[13];
    const float* ln_b = (const float*)d_in[14];
    const float* wq = (const float*)d_in[15];
    const float* bq = (const float*)d_in[16];
    const float* wk = (const float*)d_in[17];
    const float* bk = (const float*)d_in[18];
    const float* wv = (const float*)d_in[19];
    const float* bv = (const float*)d_in[20];
    const float* wo = (const float*)d_in[21];
    const float* bo = (const float*)d_in[22];
    const float* gat_w = (const float*)d_in[23];
    const float* gat_b = (const float*)d_in[24];
    const float* ga1 = (const float*)d_in[25];
    const float* ga2 = (const float*)d_in[26];
    float* out = (float*)d_out;

    __nv_bfloat16 *x3, *ms3, *z3, *ctx3, *att3, *wc3, *fpw3, *wq3, *wk3, *wv3, *wo3, *gw3;
    float *zpre, *q, *k, *v, *sc, *ctx, *hg, *e1, *e2, *e2m;
    cudaGetSymbolAddress((void**)&x3, g_x3);
    cudaGetSymbolAddress((void**)&ms3, g_ms3);
    cudaGetSymbolAddress((void**)&z3, g_z3);
    cudaGetSymbolAddress((void**)&ctx3, g_ctx3);
    cudaGetSymbolAddress((void**)&att3, g_att3);
    cudaGetSymbolAddress((void**)&wc3, g_wc3);
    cudaGetSymbolAddress((void**)&fpw3, g_fpw3);
    cudaGetSymbolAddress((void**)&wq3, g_wq3);
    cudaGetSymbolAddress((void**)&wk3, g_wk3);
    cudaGetSymbolAddress((void**)&wv3, g_wv3);
    cudaGetSymbolAddress((void**)&wo3, g_wo3);
    cudaGetSymbolAddress((void**)&gw3, g_gw3);
    cudaGetSymbolAddress((void**)&zpre, g_zpre);
    cudaGetSymbolAddress((void**)&q, g_q);
    cudaGetSymbolAddress((void**)&k, g_k);
    cudaGetSymbolAddress((void**)&v, g_v);
    cudaGetSymbolAddress((void**)&sc, g_scores);
    cudaGetSymbolAddress((void**)&ctx, g_ctx);
    cudaGetSymbolAddress((void**)&hg, g_hg);
    cudaGetSymbolAddress((void**)&e1, g_e1);
    cudaGetSymbolAddress((void**)&e2, g_e2);
    cudaGetSymbolAddress((void**)&e2m, g_e2max);

    cudaFuncSetAttribute(conv_tc, cudaFuncAttributeMaxDynamicSharedMemorySize, TC_SMEM);
    cudaFuncSetAttribute(dense_tc, cudaFuncAttributeMaxDynamicSharedMemorySize, TC_SMEM);

    // 1) splits
    split_mat<<<Nn, 256>>>(features, x3, 1024, 0);
    for (int dd = 0; dd < 5; ++dd)
        split_conv_w<<<1024, 256>>>(conv_w[dd], wc3 + (size_t)dd * 1024 * 21504);
    split_mat<<<1024, 256>>>(fp_w, fpw3, 5120, 1);
    split_mat<<<1024, 256>>>(wq, wq3, 1024, 1);
    split_mat<<<1024, 256>>>(wk, wk3, 1024, 1);
    split_mat<<<1024, 256>>>(wv, wv3, 1024, 1);
    split_mat<<<1024, 256>>>(wo, wo3, 1024, 1);
    split_mat<<<1024, 256>>>(gat_w, gw3, 1024, 1);

    // 2) conv bank (tensor cores via mma.sync) -> ms3 triple
    conv_tc<<<dim3(8, 16, 5), 256, TC_SMEM>>>(x3, wc3, conv_b[0], conv_b[1], conv_b[2],
                                              conv_b[3], conv_b[4], ms3);

    // 3) fusion projection -> zpre (fp32)
    dense_tc<<<dim3(8, 16), 256, TC_SMEM>>>(ms3, fpw3, fp_b, zpre, nullptr, 15360);

    // 4) LN + GELU -> z3 triple
    ln_gelu_kernel<<<Nn, 256>>>(zpre, ln_g, ln_b, z3);

    // 5) Q,K,V projections (fp32 out)
    dense_tc<<<dim3(8, 16), 256, TC_SMEM>>>(z3, wq3, bq, q, nullptr, 3072);
    dense_tc<<<dim3(8, 16), 256, TC_SMEM>>>(z3, wk3, bk, k, nullptr, 3072);
    dense_tc<<<dim3(8, 16), 256, TC_SMEM>>>(z3, wv3, bv, v, nullptr, 3072);

    // 6) attention scores + softmax + ctx (SIMT, small)
    gemm_nt<<<dim3(4, 4, 128), 256>>>(q, k, nullptr, sc, Tn, Tn, DH,
                                      (long long)Tn * Dm, DH, Dm, 1,
                                      (long long)Tn * Dm, DH, Dm, 1,
                                      (long long)HM * Tn * Tn, (long long)Tn * Tn, Tn,
                                      HM, 0.125f);
    softmax256<<<Bsz * HM * Tn, 256>>>(sc);
    gemm_nt<<<dim3(1, 4, 128), 256>>>(sc, v, nullptr, ctx, Tn, DH, Tn,
                                      (long long)HM * Tn * Tn, (long long)Tn * Tn, Tn, 1,
                                      (long long)Tn * Dm, DH, 1, Dm,
                                      (long long)Tn * Dm, DH, Dm,
                                      HM, 1.f);

    // 7) output projection -> att3 triple (feeds GAT GEMM only)
    split_mat<<<Nn, 256>>>(ctx, ctx3, 1024, 0);
    dense_tc<<<dim3(8, 16), 256, TC_SMEM>>>(ctx3, wo3, bo, nullptr, att3, 3072);

    // 8) GAT projection -> hg (fp32)
    dense_tc<<<dim3(8, 16), 256, TC_SMEM>>>(att3, gw3, gat_b, hg, nullptr, 3072);

    // 9) GAT logits + aggregate + residual
    e1e2_kernel<<<Nn, 256>>>(hg, ga1, ga2, e1, e2);
    e2max_kernel<<<HG, 256>>>(e2, e2m);
    gat_agg_kernel<<<dim3(Nn / TI, HG), 256>>>(hg, e1, e2, e2m, features, out);
}